// round 15
// baseline (speedup 1.0000x reference)
#include <cuda_runtime.h>
#include <cuda_fp16.h>
#include <cstdint>

constexpr int Bb = 8;
constexpr int Nn = 1024;
constexpr int Cc = 768;
constexpr int Hh = 12;
constexpr int HD = 64;
constexpr int Mm = Bb * Nn;   // 8192

// Scratch (allowed: __device__ globals, no allocation) — fp16 activations/weights
__device__ __align__(16) __half g_q[(size_t)Bb * Hh * Nn * HD];
__device__ __align__(16) __half g_k[(size_t)Bb * Hh * Nn * HD];
__device__ __align__(16) __half g_v[(size_t)Bb * Hh * Nn * HD];
__device__ __align__(16) __half g_ao[(size_t)Mm * Cc];
__device__ __align__(16) __half g_x16[(size_t)Mm * Cc];
__device__ __align__(16) __half g_wq16[(size_t)Cc * 3 * Cc];
__device__ __align__(16) __half g_wp16[(size_t)Cc * Cc];

// ---------------------------------------------------------------------------
// fused fp32 -> fp16 bulk convert (x | w_qkv | w_proj in one launch)
// ---------------------------------------------------------------------------
constexpr int CVT_N0 = Mm * Cc;                 // 6291456
constexpr int CVT_N1 = CVT_N0 + 3 * Cc * Cc;    // +1769472
constexpr int CVT_N2 = CVT_N1 + Cc * Cc;        // +589824 = 8650752

__global__ void cvt_all(const float* __restrict__ x, const float* __restrict__ wq,
                        const float* __restrict__ wp) {
    int i = (blockIdx.x * blockDim.x + threadIdx.x) * 4;
    const float* src;
    __half* dst;
    int j;
    if (i < CVT_N0) {
        src = x; dst = g_x16; j = i;
    } else if (i < CVT_N1) {
        src = wq; dst = g_wq16; j = i - CVT_N0;
    } else if (i < CVT_N2) {
        src = wp; dst = g_wp16; j = i - CVT_N1;
    } else {
        return;
    }
    float4 v = *(const float4*)(src + j);
    *(__half2*)(dst + j)     = __floats2half2_rn(v.x, v.y);
    *(__half2*)(dst + j + 2) = __floats2half2_rn(v.z, v.w);
}

// ---------------------------------------------------------------------------
// PTX helpers
// ---------------------------------------------------------------------------
__device__ __forceinline__ uint32_t smem_u32(const void* p) {
    uint32_t a;
    asm("{ .reg .u64 t; cvta.to.shared.u64 t, %1; cvt.u32.u64 %0, t; }" : "=r"(a) : "l"(p));
    return a;
}
__device__ __forceinline__ void ldsm4(uint32_t* r, uint32_t addr) {
    asm volatile("ldmatrix.sync.aligned.m8n8.x4.shared.b16 {%0,%1,%2,%3}, [%4];"
                 : "=r"(r[0]), "=r"(r[1]), "=r"(r[2]), "=r"(r[3]) : "r"(addr));
}
__device__ __forceinline__ void ldsm4t(uint32_t* r, uint32_t addr) {
    asm volatile("ldmatrix.sync.aligned.m8n8.x4.trans.shared.b16 {%0,%1,%2,%3}, [%4];"
                 : "=r"(r[0]), "=r"(r[1]), "=r"(r[2]), "=r"(r[3]) : "r"(addr));
}
__device__ __forceinline__ void mma16816(float* c, const uint32_t* a, const uint32_t* b) {
    asm volatile(
        "mma.sync.aligned.m16n8k16.row.col.f32.f16.f16.f32 "
        "{%0,%1,%2,%3}, {%4,%5,%6,%7}, {%8,%9}, {%0,%1,%2,%3};"
        : "+f"(c[0]), "+f"(c[1]), "+f"(c[2]), "+f"(c[3])
        : "r"(a[0]), "r"(a[1]), "r"(a[2]), "r"(a[3]), "r"(b[0]), "r"(b[1]));
}
__device__ __forceinline__ uint32_t packh2(float lo, float hi) {
    __half2 h = __floats2half2_rn(lo, hi);
    return *(uint32_t*)&h;
}
__device__ __forceinline__ void cp16(uint32_t saddr, const void* gaddr) {
    asm volatile("cp.async.cg.shared.global [%0], [%1], 16;" :: "r"(saddr), "l"(gaddr));
}
__device__ __forceinline__ void cp_commit() { asm volatile("cp.async.commit_group;"); }

// ---------------------------------------------------------------------------
// Raw-mma GEMM: C[M,Ncols] = A[M,768] @ Bm[768,Ncols] + bias
// CTA tile 128x256, 16 warps (4x4), warp tile 32x64, K-chunk 64,
// 3-stage cp.async pipeline, 512 threads.
// MODE 0: A = g_x16, B = g_wq16 -> scatter fp16 into g_q/g_k/g_v [B,H,N,64]
// MODE 1: A = g_ao,  B = g_wp16 -> fp32 row-major store to out
// ---------------------------------------------------------------------------
constexpr int TN = 256;
constexpr int KC = 64;                 // halves per K chunk
constexpr int NCH = Cc / KC;           // 12
constexpr int ASTR = 72;               // As row stride (halves)
constexpr int BSTR = 264;              // Bs row stride (halves)
constexpr int A_ST_BYTES = 128 * ASTR * 2;   // 18432
constexpr int B_ST_BYTES = KC * BSTR * 2;    // 33792
constexpr int STG = 3;
constexpr int OFF_B0 = STG * A_ST_BYTES;     // 55296
constexpr int GEMM_SMEM = OFF_B0 + STG * B_ST_BYTES;  // 156672

template <int MODE>
__global__ void __launch_bounds__(512, 1) gemm_kernel(const float* __restrict__ bias,
                                                      float* __restrict__ out, int Ncols) {
    extern __shared__ __align__(16) char smc[];
    const uint32_t sbase = smem_u32(smc);

    const __half* A  = (MODE == 0) ? g_x16 : g_ao;
    const __half* Bm = (MODE == 0) ? g_wq16 : g_wp16;

    const int m0 = blockIdx.y * 128;
    const int n0 = blockIdx.x * TN;
    const int tid = threadIdx.x;
    const int warp = tid >> 5;
    const int lane = tid & 31;
    const int wm = warp >> 2;   // 0..3 -> 32-row band
    const int wn = warp & 3;    // 0..3 -> 64-col band

    // ---- async loader: one K chunk (A 128x64, B 64x256) into stage ch%3 ----
    auto load_chunk = [&](int ch) {
        const int buf = ch % STG;
        const int k0 = ch * KC;
        const uint32_t abase = sbase + buf * A_ST_BYTES;
#pragma unroll
        for (int t = 0; t < 2; t++) {
            int idx = tid + t * 512;
            int r = idx >> 3, seg = idx & 7;
            cp16(abase + (uint32_t)(r * (ASTR * 2) + seg * 16),
                 A + (size_t)(m0 + r) * Cc + k0 + seg * 8);
        }
        const uint32_t bbase = sbase + OFF_B0 + buf * B_ST_BYTES;
#pragma unroll
        for (int t = 0; t < 4; t++) {
            int idx = tid + t * 512;
            int r = idx >> 5, seg = idx & 31;
            cp16(bbase + (uint32_t)(r * (BSTR * 2) + seg * 16),
                 Bm + (size_t)(k0 + r) * Ncols + n0 + seg * 8);
        }
        cp_commit();
    };

    float c[2][8][4];
#pragma unroll
    for (int mf = 0; mf < 2; mf++)
#pragma unroll
        for (int nt = 0; nt < 8; nt++)
#pragma unroll
            for (int e = 0; e < 4; e++) c[mf][nt][e] = 0.0f;

    load_chunk(0);
    load_chunk(1);
    load_chunk(2);

    const uint32_t a_row = (uint32_t)(wm * 32) + (lane & 15);
    const uint32_t a_coff = (uint32_t)(lane >> 4) * 8;
    const uint32_t b_krow = (uint32_t)(lane & 15);
    const uint32_t b_coff = (uint32_t)(wn * 64) + (uint32_t)(lane >> 4) * 8;

    for (int ch = 0; ch < NCH; ch++) {
        if (ch < NCH - 2) {
            asm volatile("cp.async.wait_group 2;" ::: "memory");
        } else if (ch == NCH - 2) {
            asm volatile("cp.async.wait_group 1;" ::: "memory");
        } else {
            asm volatile("cp.async.wait_group 0;" ::: "memory");
        }
        __syncthreads();

        const int buf = ch % STG;
        const uint32_t abase = sbase + buf * A_ST_BYTES;
        const uint32_t bbase = sbase + OFF_B0 + buf * B_ST_BYTES;
#pragma unroll
        for (int kk = 0; kk < 4; kk++) {
            uint32_t a[2][4];
#pragma unroll
            for (int mf = 0; mf < 2; mf++)
                ldsm4(a[mf], abase + ((a_row + mf * 16) * ASTR + kk * 16 + a_coff) * 2);
            uint32_t b[4][4];
#pragma unroll
            for (int np = 0; np < 4; np++)
                ldsm4t(b[np], bbase + ((kk * 16 + b_krow) * BSTR + b_coff + np * 16) * 2);
#pragma unroll
            for (int mf = 0; mf < 2; mf++)
#pragma unroll
                for (int nt = 0; nt < 8; nt++)
                    mma16816(c[mf][nt], a[mf], b[nt >> 1] + (nt & 1) * 2);
        }
        __syncthreads();
        if (ch + STG < NCH) load_chunk(ch + STG);
    }

    // ---- epilogue: bias + store ----
    const int ncol0 = n0 + wn * 64;
    float2 bias2[8];
#pragma unroll
    for (int nt = 0; nt < 8; nt++) {
        const int n = ncol0 + nt * 8 + (lane & 3) * 2;
        bias2[nt] = *(const float2*)(bias + n);
    }

    if (MODE == 1) {
#pragma unroll
        for (int mf = 0; mf < 2; mf++) {
            const int r0 = m0 + wm * 32 + mf * 16 + (lane >> 2);
#pragma unroll
            for (int nt = 0; nt < 8; nt++) {
                const int n = ncol0 + nt * 8 + (lane & 3) * 2;
                *(float2*)(out + (size_t)r0 * Ncols + n) =
                    make_float2(c[mf][nt][0] + bias2[nt].x, c[mf][nt][1] + bias2[nt].y);
                *(float2*)(out + (size_t)(r0 + 8) * Ncols + n) =
                    make_float2(c[mf][nt][2] + bias2[nt].x, c[mf][nt][3] + bias2[nt].y);
            }
        }
    } else {
        const int which = ncol0 / Cc;
        const int rem = ncol0 % Cc;
        const int h = rem >> 6;
        __half* arr = (which == 0) ? g_q : (which == 1) ? g_k : g_v;
#pragma unroll
        for (int mf = 0; mf < 2; mf++) {
            const int r0 = m0 + wm * 32 + mf * 16 + (lane >> 2);
            const int b0 = r0 >> 10, nr0 = r0 & 1023;
            const int r1 = r0 + 8;
            const int b1 = r1 >> 10, nr1 = r1 & 1023;
            __half* p0 = arr + (size_t)((b0 * Hh + h) * Nn + nr0) * HD;
            __half* p1 = arr + (size_t)((b1 * Hh + h) * Nn + nr1) * HD;
#pragma unroll
            for (int nt = 0; nt < 8; nt++) {
                const int d = (rem & 63) + nt * 8 + (lane & 3) * 2;
                *(__half2*)(p0 + d) =
                    __floats2half2_rn(c[mf][nt][0] + bias2[nt].x, c[mf][nt][1] + bias2[nt].y);
                *(__half2*)(p1 + d) =
                    __floats2half2_rn(c[mf][nt][2] + bias2[nt].x, c[mf][nt][3] + bias2[nt].y);
            }
        }
    }
}

// ---------------------------------------------------------------------------
// Flash attention, FA2-style register-resident (unchanged from R13/R14).
// ---------------------------------------------------------------------------
constexpr int KT = 64;

__global__ void __launch_bounds__(256, 2) attn_kernel() {
    __shared__ __align__(16) __half Qs[128][72];
    __shared__ __align__(16) __half Ks[KT][72];
    __shared__ __align__(16) __half Vs[KT][72];

    const int tid = threadIdx.x;
    const int warp = tid >> 5;
    const int lane = tid & 31;
    const int n0 = blockIdx.x * 128;
    const int bh = blockIdx.y;
    const __half* Qg = g_q + (size_t)bh * Nn * HD;
    const __half* Kg = g_k + (size_t)bh * Nn * HD;
    const __half* Vg = g_v + (size_t)bh * Nn * HD;

    const __half2 sc = __floats2half2_rn(0.125f, 0.125f);
#pragma unroll
    for (int t = 0; t < 4; t++) {
        int idx = tid + t * 256;
        int r = idx >> 3, g = idx & 7;
        uint4 u = *(const uint4*)(Qg + (size_t)(n0 + r) * HD + g * 8);
        __half2* h = (__half2*)&u;
#pragma unroll
        for (int e = 0; e < 4; e++) h[e] = __hmul2(h[e], sc);
        *(uint4*)&Qs[r][g * 8] = u;
    }
    __syncthreads();

    uint32_t qa[4][4];
    {
        const uint32_t qs_u = smem_u32(&Qs[0][0]);
        const uint32_t row = warp * 16 + (lane & 15);
        const uint32_t coff = (lane >> 4) * 8;
#pragma unroll
        for (int kk = 0; kk < 4; kk++)
            ldsm4(qa[kk], qs_u + (row * 72 + kk * 16 + coff) * 2);
    }

    float o[8][4];
#pragma unroll
    for (int h = 0; h < 8; h++)
#pragma unroll
        for (int e = 0; e < 4; e++) o[h][e] = 0.0f;
    float m0 = -1e30f, m1 = -1e30f, l0 = 0.0f, l1 = 0.0f;

    const uint32_t ks_u = smem_u32(&Ks[0][0]);
    const uint32_t vs_u = smem_u32(&Vs[0][0]);
    const uint32_t krow = (lane & 7);
    const uint32_t kcol = (lane >> 3) * 8;

    for (int kt = 0; kt < Nn / KT; kt++) {
        __syncthreads();
#pragma unroll
        for (int t = 0; t < 2; t++) {
            int idx = tid + t * 256;
            int r = idx >> 3, g = idx & 7;
            *(uint4*)&Ks[r][g * 8] = *(const uint4*)(Kg + (size_t)(kt * KT + r) * HD + g * 8);
            *(uint4*)&Vs[r][g * 8] = *(const uint4*)(Vg + (size_t)(kt * KT + r) * HD + g * 8);
        }
        __syncthreads();

        float s[8][4];
#pragma unroll
        for (int j = 0; j < 8; j++) {
            s[j][0] = s[j][1] = s[j][2] = s[j][3] = 0.0f;
            const uint32_t base = ks_u + (((j * 8 + krow) * 72) + kcol) * 2;
            uint32_t kr[4];
            ldsm4(kr, base);
            mma16816(s[j], qa[0], kr);
            mma16816(s[j], qa[1], kr + 2);
            ldsm4(kr, base + 64);
            mma16816(s[j], qa[2], kr);
            mma16816(s[j], qa[3], kr + 2);
        }

        float mx0 = -1e30f, mx1 = -1e30f;
#pragma unroll
        for (int j = 0; j < 8; j++) {
            mx0 = fmaxf(mx0, fmaxf(s[j][0], s[j][1]));
            mx1 = fmaxf(mx1, fmaxf(s[j][2], s[j][3]));
        }
        mx0 = fmaxf(mx0, __shfl_xor_sync(0xffffffffu, mx0, 1));
        mx0 = fmaxf(mx0, __shfl_xor_sync(0xffffffffu, mx0, 2));
        mx1 = fmaxf(mx1, __shfl_xor_sync(0xffffffffu, mx1, 1));
        mx1 = fmaxf(mx1, __shfl_xor_sync(0xffffffffu, mx1, 2));
        const float mn0 = fmaxf(m0, mx0), mn1 = fmaxf(m1, mx1);
        const float al0 = __expf(m0 - mn0), al1 = __expf(m1 - mn1);
        m0 = mn0; m1 = mn1;

        float sl0 = 0.0f, sl1 = 0.0f;
        uint32_t pa[4][4];
#pragma unroll
        for (int j = 0; j < 8; j++) {
            float p0 = __expf(s[j][0] - mn0);
            float p1 = __expf(s[j][1] - mn0);
            float p2 = __expf(s[j][2] - mn1);
            float p3 = __expf(s[j][3] - mn1);
            sl0 += p0 + p1;
            sl1 += p2 + p3;
            pa[j >> 1][(j & 1) * 2]     = packh2(p0, p1);
            pa[j >> 1][(j & 1) * 2 + 1] = packh2(p2, p3);
        }
        sl0 += __shfl_xor_sync(0xffffffffu, sl0, 1);
        sl0 += __shfl_xor_sync(0xffffffffu, sl0, 2);
        sl1 += __shfl_xor_sync(0xffffffffu, sl1, 1);
        sl1 += __shfl_xor_sync(0xffffffffu, sl1, 2);
        l0 = l0 * al0 + sl0;
        l1 = l1 * al1 + sl1;
#pragma unroll
        for (int h = 0; h < 8; h++) {
            o[h][0] *= al0; o[h][1] *= al0;
            o[h][2] *= al1; o[h][3] *= al1;
        }

#pragma unroll
        for (int kk = 0; kk < 4; kk++) {
            const uint32_t vbase = vs_u + (((kk * 16 + (lane & 15)) * 72) + (lane >> 4) * 8) * 2;
#pragma unroll
            for (int hp = 0; hp < 4; hp++) {
                uint32_t vr[4];
                ldsm4t(vr, vbase + hp * 32);
                mma16816(o[2 * hp],     pa[kk], vr);
                mma16816(o[2 * hp + 1], pa[kk], vr + 2);
            }
        }
    }

    const int b = bh / Hh, head = bh % Hh;
    const float inv0 = 1.0f / l0, inv1 = 1.0f / l1;
    const int row0 = n0 + warp * 16 + (lane >> 2);
    __half* po0 = g_ao + (size_t)(b * Nn + row0) * Cc + head * HD;
    __half* po1 = po0 + (size_t)8 * Cc;
    const int cb = (lane & 3) * 2;
#pragma unroll
    for (int h = 0; h < 8; h++) {
        *(__half2*)(po0 + h * 8 + cb) = __floats2half2_rn(o[h][0] * inv0, o[h][1] * inv0);
        *(__half2*)(po1 + h * 8 + cb) = __floats2half2_rn(o[h][2] * inv1, o[h][3] * inv1);
    }
}

// ---------------------------------------------------------------------------
extern "C" void kernel_launch(void* const* d_in, const int* in_sizes, int n_in,
                              void* d_out, int out_size) {
    const float* x      = (const float*)d_in[0];
    const float* w_qkv  = (const float*)d_in[1];
    const float* b_qkv  = (const float*)d_in[2];
    const float* w_proj = (const float*)d_in[3];
    const float* b_proj = (const float*)d_in[4];
    float* out = (float*)d_out;

    static bool attr_set = false;
    if (!attr_set) {
        cudaFuncSetAttribute(gemm_kernel<0>, cudaFuncAttributeMaxDynamicSharedMemorySize,
                             GEMM_SMEM);
        cudaFuncSetAttribute(gemm_kernel<1>, cudaFuncAttributeMaxDynamicSharedMemorySize,
                             GEMM_SMEM);
        attr_set = true;
    }

    // 0) fused fp32->fp16 converts
    cvt_all<<<(CVT_N2 / 4 + 255) / 256, 256>>>(x, w_qkv, w_proj);

    // 1) QKV GEMM: [8192,768] @ [768,2304] + bias -> fp16 scatter to Q/K/V
    gemm_kernel<0><<<dim3((3 * Cc) / TN, Mm / 128), 512, GEMM_SMEM>>>(b_qkv, nullptr, 3 * Cc);
    // 2) attention per (bh, 128-q-tile)
    attn_kernel<<<dim3(Nn / 128, Bb * Hh), 256>>>();
    // 3) output projection: [8192,768] @ [768,768] + bias -> d_out (fp32)
    gemm_kernel<1><<<dim3(Cc / TN, Mm / 128), 512, GEMM_SMEM>>>(b_proj, out, Cc);
}

// round 16
// speedup vs baseline: 1.0697x; 1.0697x over previous
#include <cuda_runtime.h>
#include <cuda_fp16.h>
#include <cstdint>

constexpr int Bb = 8;
constexpr int Nn = 1024;
constexpr int Cc = 768;
constexpr int Hh = 12;
constexpr int HD = 64;
constexpr int Mm = Bb * Nn;   // 8192

// Scratch (allowed: __device__ globals, no allocation) — fp16 activations/weights
__device__ __align__(16) __half g_q[(size_t)Bb * Hh * Nn * HD];
__device__ __align__(16) __half g_k[(size_t)Bb * Hh * Nn * HD];
__device__ __align__(16) __half g_v[(size_t)Bb * Hh * Nn * HD];
__device__ __align__(16) __half g_ao[(size_t)Mm * Cc];
__device__ __align__(16) __half g_x16[(size_t)Mm * Cc];
__device__ __align__(16) __half g_wq16[(size_t)Cc * 3 * Cc];
__device__ __align__(16) __half g_wp16[(size_t)Cc * Cc];

// ---------------------------------------------------------------------------
// fused fp32 -> fp16 bulk convert (x | w_qkv | w_proj in one launch)
// ---------------------------------------------------------------------------
constexpr int CVT_N0 = Mm * Cc;
constexpr int CVT_N1 = CVT_N0 + 3 * Cc * Cc;
constexpr int CVT_N2 = CVT_N1 + Cc * Cc;

__global__ void cvt_all(const float* __restrict__ x, const float* __restrict__ wq,
                        const float* __restrict__ wp) {
    int i = (blockIdx.x * blockDim.x + threadIdx.x) * 4;
    const float* src;
    __half* dst;
    int j;
    if (i < CVT_N0) {
        src = x; dst = g_x16; j = i;
    } else if (i < CVT_N1) {
        src = wq; dst = g_wq16; j = i - CVT_N0;
    } else if (i < CVT_N2) {
        src = wp; dst = g_wp16; j = i - CVT_N1;
    } else {
        return;
    }
    float4 v = *(const float4*)(src + j);
    *(__half2*)(dst + j)     = __floats2half2_rn(v.x, v.y);
    *(__half2*)(dst + j + 2) = __floats2half2_rn(v.z, v.w);
}

// ---------------------------------------------------------------------------
// PTX helpers
// ---------------------------------------------------------------------------
__device__ __forceinline__ uint32_t smem_u32(const void* p) {
    uint32_t a;
    asm("{ .reg .u64 t; cvta.to.shared.u64 t, %1; cvt.u32.u64 %0, t; }" : "=r"(a) : "l"(p));
    return a;
}
__device__ __forceinline__ void ldsm4(uint32_t* r, uint32_t addr) {
    asm volatile("ldmatrix.sync.aligned.m8n8.x4.shared.b16 {%0,%1,%2,%3}, [%4];"
                 : "=r"(r[0]), "=r"(r[1]), "=r"(r[2]), "=r"(r[3]) : "r"(addr));
}
__device__ __forceinline__ void ldsm4t(uint32_t* r, uint32_t addr) {
    asm volatile("ldmatrix.sync.aligned.m8n8.x4.trans.shared.b16 {%0,%1,%2,%3}, [%4];"
                 : "=r"(r[0]), "=r"(r[1]), "=r"(r[2]), "=r"(r[3]) : "r"(addr));
}
__device__ __forceinline__ void mma16816(float* c, const uint32_t* a, const uint32_t* b) {
    asm volatile(
        "mma.sync.aligned.m16n8k16.row.col.f32.f16.f16.f32 "
        "{%0,%1,%2,%3}, {%4,%5,%6,%7}, {%8,%9}, {%0,%1,%2,%3};"
        : "+f"(c[0]), "+f"(c[1]), "+f"(c[2]), "+f"(c[3])
        : "r"(a[0]), "r"(a[1]), "r"(a[2]), "r"(a[3]), "r"(b[0]), "r"(b[1]));
}
__device__ __forceinline__ uint32_t packh2(float lo, float hi) {
    __half2 h = __floats2half2_rn(lo, hi);
    return *(uint32_t*)&h;
}
__device__ __forceinline__ void cp16(uint32_t saddr, const void* gaddr) {
    asm volatile("cp.async.cg.shared.global [%0], [%1], 16;" :: "r"(saddr), "l"(gaddr));
}
__device__ __forceinline__ void cp_commit() { asm volatile("cp.async.commit_group;"); }

// ---------------------------------------------------------------------------
// Raw-mma GEMM: C[M,Ncols] = A[M,768] @ Bm[768,Ncols] + bias
// CTA tile 128xTN, 8 warps (2x4), warp tile 64x(TN/4), K-chunk 64,
// 2-stage cp.async double buffer, 256 threads. (R14-measured config)
// MODE 0 (TN=256): A = g_x16, B = g_wq16 -> fp16 scatter into g_q/g_k/g_v
// MODE 1 (TN=128): A = g_ao,  B = g_wp16 -> fp32 row-major store to out
// ---------------------------------------------------------------------------
constexpr int KC = 64;
constexpr int NCH = Cc / KC;           // 12
constexpr int ASTR = 72;
constexpr int A_ST_BYTES = 128 * ASTR * 2;   // 18432
constexpr int gemm_smem(int TN) { return 2 * A_ST_BYTES + 2 * KC * (TN + 8) * 2; }

template <int MODE, int TN>
__global__ void __launch_bounds__(256, 1) gemm_kernel(const float* __restrict__ bias,
                                                      float* __restrict__ out, int Ncols) {
    extern __shared__ __align__(16) char smc[];
    const uint32_t sbase = smem_u32(smc);

    constexpr int BSTR = TN + 8;                  // halves
    constexpr int B_ST_BYTES = KC * BSTR * 2;
    constexpr int OFF_B0 = 2 * A_ST_BYTES;
    constexpr int BSEG = TN / 8;                  // 16B segments per B row
    constexpr int BSH = (TN == 256) ? 5 : 4;
    constexpr int NTF = TN / 32;                  // n8-tiles per warp
    constexpr int NP = TN / 64;                   // ldsm4t groups per warp

    const __half* A  = (MODE == 0) ? g_x16 : g_ao;
    const __half* Bm = (MODE == 0) ? g_wq16 : g_wp16;

    const int m0 = blockIdx.y * 128;
    const int n0 = blockIdx.x * TN;
    const int tid = threadIdx.x;
    const int warp = tid >> 5;
    const int lane = tid & 31;
    const int wm = warp >> 2;   // 0..1 -> 64-row band
    const int wn = warp & 3;    // 0..3 -> (TN/4)-col band

    auto load_chunk = [&](int ch, int buf) {
        const int k0 = ch * KC;
        const uint32_t abase = sbase + buf * A_ST_BYTES;
#pragma unroll
        for (int t = 0; t < 4; t++) {
            int idx = tid + t * 256;
            int r = idx >> 3, seg = idx & 7;
            cp16(abase + (uint32_t)(r * (ASTR * 2) + seg * 16),
                 A + (size_t)(m0 + r) * Cc + k0 + seg * 8);
        }
        const uint32_t bbase = sbase + OFF_B0 + buf * B_ST_BYTES;
#pragma unroll
        for (int t = 0; t < (KC * BSEG) / 256; t++) {
            int idx = tid + t * 256;
            int r = idx >> BSH, seg = idx & (BSEG - 1);
            cp16(bbase + (uint32_t)(r * (BSTR * 2) + seg * 16),
                 Bm + (size_t)(k0 + r) * Ncols + n0 + seg * 8);
        }
        cp_commit();
    };

    float c[4][NTF][4];
#pragma unroll
    for (int mf = 0; mf < 4; mf++)
#pragma unroll
        for (int nt = 0; nt < NTF; nt++)
#pragma unroll
            for (int e = 0; e < 4; e++) c[mf][nt][e] = 0.0f;

    load_chunk(0, 0);
    load_chunk(1, 1);

    const uint32_t a_row = (uint32_t)(wm * 64) + (lane & 15);
    const uint32_t a_coff = (uint32_t)(lane >> 4) * 8;
    const uint32_t b_krow = (uint32_t)(lane & 15);
    const uint32_t b_coff = (uint32_t)(wn * (TN / 4)) + (uint32_t)(lane >> 4) * 8;

    for (int ch = 0; ch < NCH; ch++) {
        const int buf = ch & 1;
        if (ch + 1 < NCH) {
            asm volatile("cp.async.wait_group 1;" ::: "memory");
        } else {
            asm volatile("cp.async.wait_group 0;" ::: "memory");
        }
        __syncthreads();

        const uint32_t abase = sbase + buf * A_ST_BYTES;
        const uint32_t bbase = sbase + OFF_B0 + buf * B_ST_BYTES;
#pragma unroll
        for (int kk = 0; kk < 4; kk++) {
            uint32_t a[4][4];
#pragma unroll
            for (int mf = 0; mf < 4; mf++)
                ldsm4(a[mf], abase + ((a_row + mf * 16) * ASTR + kk * 16 + a_coff) * 2);
            uint32_t b[NP][4];
#pragma unroll
            for (int np = 0; np < NP; np++)
                ldsm4t(b[np], bbase + ((kk * 16 + b_krow) * BSTR + b_coff + np * 16) * 2);
#pragma unroll
            for (int mf = 0; mf < 4; mf++)
#pragma unroll
                for (int nt = 0; nt < NTF; nt++)
                    mma16816(c[mf][nt], a[mf], b[nt >> 1] + (nt & 1) * 2);
        }
        __syncthreads();
        if (ch + 2 < NCH) load_chunk(ch + 2, buf);
    }

    // ---- epilogue: bias + store ----
    const int ncol0 = n0 + wn * (TN / 4);
    float2 bias2[NTF];
#pragma unroll
    for (int nt = 0; nt < NTF; nt++) {
        const int n = ncol0 + nt * 8 + (lane & 3) * 2;
        bias2[nt] = *(const float2*)(bias + n);
    }

    if (MODE == 1) {
#pragma unroll
        for (int mf = 0; mf < 4; mf++) {
            const int r0 = m0 + wm * 64 + mf * 16 + (lane >> 2);
#pragma unroll
            for (int nt = 0; nt < NTF; nt++) {
                const int n = ncol0 + nt * 8 + (lane & 3) * 2;
                *(float2*)(out + (size_t)r0 * Ncols + n) =
                    make_float2(c[mf][nt][0] + bias2[nt].x, c[mf][nt][1] + bias2[nt].y);
                *(float2*)(out + (size_t)(r0 + 8) * Ncols + n) =
                    make_float2(c[mf][nt][2] + bias2[nt].x, c[mf][nt][3] + bias2[nt].y);
            }
        }
    } else {
        // TN=256: warp band = 64 cols inside one 64-wide head chunk
        const int which = ncol0 / Cc;
        const int rem = ncol0 % Cc;
        const int h = rem >> 6;
        __half* arr = (which == 0) ? g_q : (which == 1) ? g_k : g_v;
#pragma unroll
        for (int mf = 0; mf < 4; mf++) {
            const int r0 = m0 + wm * 64 + mf * 16 + (lane >> 2);
            const int b0 = r0 >> 10, nr0 = r0 & 1023;
            const int r1 = r0 + 8;
            const int b1 = r1 >> 10, nr1 = r1 & 1023;
            __half* p0 = arr + (size_t)((b0 * Hh + h) * Nn + nr0) * HD;
            __half* p1 = arr + (size_t)((b1 * Hh + h) * Nn + nr1) * HD;
#pragma unroll
            for (int nt = 0; nt < NTF; nt++) {
                const int d = (rem & 63) + nt * 8 + (lane & 3) * 2;
                *(__half2*)(p0 + d) =
                    __floats2half2_rn(c[mf][nt][0] + bias2[nt].x, c[mf][nt][1] + bias2[nt].y);
                *(__half2*)(p1 + d) =
                    __floats2half2_rn(c[mf][nt][2] + bias2[nt].x, c[mf][nt][3] + bias2[nt].y);
            }
        }
    }
}

// ---------------------------------------------------------------------------
// Flash attention, FA2-style register-resident, cp.async double-buffered K/V.
// CTA: 8 warps, 128 q-rows (16/warp); K-tile = 64 keys; 16 iterations.
// ---------------------------------------------------------------------------
constexpr int KT = 64;
constexpr int NIT = Nn / KT;              // 16
constexpr int Q_BYTES = 128 * 72 * 2;     // 18432
constexpr int KV_ST = KT * 72 * 2;        // 9216 per stage
constexpr int OFF_K = Q_BYTES;            // K stages at 18432, 27648
constexpr int OFF_V = OFF_K + 2 * KV_ST;  // V stages at 36864, 46080
constexpr int ATTN_SMEM = OFF_V + 2 * KV_ST;  // 55296

__global__ void __launch_bounds__(256, 2) attn_kernel() {
    extern __shared__ __align__(16) char smc[];
    const uint32_t sb = smem_u32(smc);
    __half* Qs = (__half*)smc;  // [128][72]

    const int tid = threadIdx.x;
    const int warp = tid >> 5;
    const int lane = tid & 31;
    const int n0 = blockIdx.x * 128;
    const int bh = blockIdx.y;
    const __half* Qg = g_q + (size_t)bh * Nn * HD;
    const __half* Kg = g_k + (size_t)bh * Nn * HD;
    const __half* Vg = g_v + (size_t)bh * Nn * HD;

    auto load_kv = [&](int kt, int buf) {
        const __half* Kp = Kg + (size_t)(kt * KT) * HD;
        const __half* Vp = Vg + (size_t)(kt * KT) * HD;
        const uint32_t kb = sb + OFF_K + buf * KV_ST;
        const uint32_t vb = sb + OFF_V + buf * KV_ST;
#pragma unroll
        for (int t = 0; t < 2; t++) {
            int idx = tid + t * 256;
            int r = idx >> 3, g = idx & 7;
            cp16(kb + (uint32_t)(r * 144 + g * 16), Kp + r * HD + g * 8);
            cp16(vb + (uint32_t)(r * 144 + g * 16), Vp + r * HD + g * 8);
        }
        cp_commit();
    };

    // get tile 0 in flight before anything else
    load_kv(0, 0);

    // ---- load Q tile (pre-scaled by 0.125) ----
    const __half2 sc = __floats2half2_rn(0.125f, 0.125f);
#pragma unroll
    for (int t = 0; t < 4; t++) {
        int idx = tid + t * 256;
        int r = idx >> 3, g = idx & 7;
        uint4 u = *(const uint4*)(Qg + (size_t)(n0 + r) * HD + g * 8);
        __half2* h = (__half2*)&u;
#pragma unroll
        for (int e = 0; e < 4; e++) h[e] = __hmul2(h[e], sc);
        *(uint4*)&Qs[r * 72 + g * 8] = u;
    }
    __syncthreads();

    uint32_t qa[4][4];
    {
        const uint32_t row = warp * 16 + (lane & 15);
        const uint32_t coff = (lane >> 4) * 8;
#pragma unroll
        for (int kk = 0; kk < 4; kk++)
            ldsm4(qa[kk], sb + (row * 72 + kk * 16 + coff) * 2);
    }

    float o[8][4];
#pragma unroll
    for (int h = 0; h < 8; h++)
#pragma unroll
        for (int e = 0; e < 4; e++) o[h][e] = 0.0f;
    float m0 = -1e30f, m1 = -1e30f, l0 = 0.0f, l1 = 0.0f;

    const uint32_t krow = (lane & 7);
    const uint32_t kcol = (lane >> 3) * 8;

    for (int kt = 0; kt < NIT; kt++) {
        const int buf = kt & 1;
        if (kt + 1 < NIT) {
            load_kv(kt + 1, buf ^ 1);   // prefetch next tile (buffer freed by last iter's end-sync)
            asm volatile("cp.async.wait_group 1;" ::: "memory");   // tile kt landed
        } else {
            asm volatile("cp.async.wait_group 0;" ::: "memory");
        }
        __syncthreads();

        const uint32_t ks_u = sb + OFF_K + buf * KV_ST;
        const uint32_t vs_u = sb + OFF_V + buf * KV_ST;

        // ---- S = Q K^T : 8 key-tiles (n8) x 4 k-steps ----
        float s[8][4];
#pragma unroll
        for (int j = 0; j < 8; j++) {
            s[j][0] = s[j][1] = s[j][2] = s[j][3] = 0.0f;
            const uint32_t base = ks_u + (((j * 8 + krow) * 72) + kcol) * 2;
            uint32_t kr[4];
            ldsm4(kr, base);
            mma16816(s[j], qa[0], kr);
            mma16816(s[j], qa[1], kr + 2);
            ldsm4(kr, base + 64);
            mma16816(s[j], qa[2], kr);
            mma16816(s[j], qa[3], kr + 2);
        }

        // ---- online softmax in registers ----
        float mx0 = -1e30f, mx1 = -1e30f;
#pragma unroll
        for (int j = 0; j < 8; j++) {
            mx0 = fmaxf(mx0, fmaxf(s[j][0], s[j][1]));
            mx1 = fmaxf(mx1, fmaxf(s[j][2], s[j][3]));
        }
        mx0 = fmaxf(mx0, __shfl_xor_sync(0xffffffffu, mx0, 1));
        mx0 = fmaxf(mx0, __shfl_xor_sync(0xffffffffu, mx0, 2));
        mx1 = fmaxf(mx1, __shfl_xor_sync(0xffffffffu, mx1, 1));
        mx1 = fmaxf(mx1, __shfl_xor_sync(0xffffffffu, mx1, 2));
        const float mn0 = fmaxf(m0, mx0), mn1 = fmaxf(m1, mx1);
        const float al0 = __expf(m0 - mn0), al1 = __expf(m1 - mn1);
        m0 = mn0; m1 = mn1;

        float sl0 = 0.0f, sl1 = 0.0f;
        uint32_t pa[4][4];
#pragma unroll
        for (int j = 0; j < 8; j++) {
            float p0 = __expf(s[j][0] - mn0);
            float p1 = __expf(s[j][1] - mn0);
            float p2 = __expf(s[j][2] - mn1);
            float p3 = __expf(s[j][3] - mn1);
            sl0 += p0 + p1;
            sl1 += p2 + p3;
            pa[j >> 1][(j & 1) * 2]     = packh2(p0, p1);
            pa[j >> 1][(j & 1) * 2 + 1] = packh2(p2, p3);
        }
        sl0 += __shfl_xor_sync(0xffffffffu, sl0, 1);
        sl0 += __shfl_xor_sync(0xffffffffu, sl0, 2);
        sl1 += __shfl_xor_sync(0xffffffffu, sl1, 1);
        sl1 += __shfl_xor_sync(0xffffffffu, sl1, 2);
        l0 = l0 * al0 + sl0;
        l1 = l1 * al1 + sl1;
#pragma unroll
        for (int h = 0; h < 8; h++) {
            o[h][0] *= al0; o[h][1] *= al0;
            o[h][2] *= al1; o[h][3] *= al1;
        }

        // ---- O += P V ----
#pragma unroll
        for (int kk = 0; kk < 4; kk++) {
            const uint32_t vbase = vs_u + (((kk * 16 + (lane & 15)) * 72) + (lane >> 4) * 8) * 2;
#pragma unroll
            for (int hp = 0; hp < 4; hp++) {
                uint32_t vr[4];
                ldsm4t(vr, vbase + hp * 32);
                mma16816(o[2 * hp],     pa[kk], vr);
                mma16816(o[2 * hp + 1], pa[kk], vr + 2);
            }
        }
        __syncthreads();   // all reads of buf done before it is overwritten
    }

    // ---- epilogue: normalize, write fp16 to g_ao ----
    const int b = bh / Hh, head = bh % Hh;
    const float inv0 = 1.0f / l0, inv1 = 1.0f / l1;
    const int row0 = n0 + warp * 16 + (lane >> 2);
    __half* po0 = g_ao + (size_t)(b * Nn + row0) * Cc + head * HD;
    __half* po1 = po0 + (size_t)8 * Cc;
    const int cb = (lane & 3) * 2;
#pragma unroll
    for (int h = 0; h < 8; h++) {
        *(__half2*)(po0 + h * 8 + cb) = __floats2half2_rn(o[h][0] * inv0, o[h][1] * inv0);
        *(__half2*)(po1 + h * 8 + cb) = __floats2half2_rn(o[h][2] * inv1, o[h][3] * inv1);
    }
}

// ---------------------------------------------------------------------------
extern "C" void kernel_launch(void* const* d_in, const int* in_sizes, int n_in,
                              void* d_out, int out_size) {
    const float* x      = (const float*)d_in[0];
    const float* w_qkv  = (const float*)d_in[1];
    const float* b_qkv  = (const float*)d_in[2];
    const float* w_proj = (const float*)d_in[3];
    const float* b_proj = (const float*)d_in[4];
    float* out = (float*)d_out;

    static bool attr_set = false;
    if (!attr_set) {
        cudaFuncSetAttribute(gemm_kernel<0, 256>, cudaFuncAttributeMaxDynamicSharedMemorySize,
                             gemm_smem(256));
        cudaFuncSetAttribute(gemm_kernel<1, 128>, cudaFuncAttributeMaxDynamicSharedMemorySize,
                             gemm_smem(128));
        cudaFuncSetAttribute(attn_kernel, cudaFuncAttributeMaxDynamicSharedMemorySize,
                             ATTN_SMEM);
        attr_set = true;
    }

    // 0) fused fp32->fp16 converts
    cvt_all<<<(CVT_N2 / 4 + 255) / 256, 256>>>(x, w_qkv, w_proj);

    // 1) QKV GEMM: [8192,768] @ [768,2304] + bias -> fp16 scatter to Q/K/V
    gemm_kernel<0, 256><<<dim3((3 * Cc) / 256, Mm / 128), 256, gemm_smem(256)>>>(
        b_qkv, nullptr, 3 * Cc);
    // 2) attention per (bh, 128-q-tile)
    attn_kernel<<<dim3(Nn / 128, Bb * Hh), 256, ATTN_SMEM>>>();
    // 3) output projection: [8192,768] @ [768,768] + bias -> d_out (fp32), 128x128 tiles
    gemm_kernel<1, 128><<<dim3(Cc / 128, Mm / 128), 256, gemm_smem(128)>>>(b_proj, out, Cc);
}

// round 17
// speedup vs baseline: 1.1229x; 1.0498x over previous
#include <cuda_runtime.h>
#include <cuda_fp16.h>
#include <cstdint>

constexpr int Bb = 8;
constexpr int Nn = 1024;
constexpr int Cc = 768;
constexpr int Hh = 12;
constexpr int HD = 64;
constexpr int Mm = Bb * Nn;   // 8192

// Scratch (allowed: __device__ globals, no allocation) — fp16 activations/weights
__device__ __align__(16) __half g_q[(size_t)Bb * Hh * Nn * HD];
__device__ __align__(16) __half g_k[(size_t)Bb * Hh * Nn * HD];
__device__ __align__(16) __half g_v[(size_t)Bb * Hh * Nn * HD];
__device__ __align__(16) __half g_ao[(size_t)Mm * Cc];
__device__ __align__(16) __half g_x16[(size_t)Mm * Cc];
__device__ __align__(16) __half g_wq16[(size_t)Cc * 3 * Cc];
__device__ __align__(16) __half g_wp16[(size_t)Cc * Cc];

// ---------------------------------------------------------------------------
// fused fp32 -> fp16 bulk convert (x | w_qkv | w_proj in one launch)
// ---------------------------------------------------------------------------
constexpr int CVT_N0 = Mm * Cc;
constexpr int CVT_N1 = CVT_N0 + 3 * Cc * Cc;
constexpr int CVT_N2 = CVT_N1 + Cc * Cc;

__global__ void cvt_all(const float* __restrict__ x, const float* __restrict__ wq,
                        const float* __restrict__ wp) {
    int i = (blockIdx.x * blockDim.x + threadIdx.x) * 4;
    const float* src;
    __half* dst;
    int j;
    if (i < CVT_N0) {
        src = x; dst = g_x16; j = i;
    } else if (i < CVT_N1) {
        src = wq; dst = g_wq16; j = i - CVT_N0;
    } else if (i < CVT_N2) {
        src = wp; dst = g_wp16; j = i - CVT_N1;
    } else {
        return;
    }
    float4 v = *(const float4*)(src + j);
    *(__half2*)(dst + j)     = __floats2half2_rn(v.x, v.y);
    *(__half2*)(dst + j + 2) = __floats2half2_rn(v.z, v.w);
}

// ---------------------------------------------------------------------------
// PTX helpers
// ---------------------------------------------------------------------------
__device__ __forceinline__ uint32_t smem_u32(const void* p) {
    uint32_t a;
    asm("{ .reg .u64 t; cvta.to.shared.u64 t, %1; cvt.u32.u64 %0, t; }" : "=r"(a) : "l"(p));
    return a;
}
__device__ __forceinline__ void ldsm4(uint32_t* r, uint32_t addr) {
    asm volatile("ldmatrix.sync.aligned.m8n8.x4.shared.b16 {%0,%1,%2,%3}, [%4];"
                 : "=r"(r[0]), "=r"(r[1]), "=r"(r[2]), "=r"(r[3]) : "r"(addr));
}
__device__ __forceinline__ void ldsm4t(uint32_t* r, uint32_t addr) {
    asm volatile("ldmatrix.sync.aligned.m8n8.x4.trans.shared.b16 {%0,%1,%2,%3}, [%4];"
                 : "=r"(r[0]), "=r"(r[1]), "=r"(r[2]), "=r"(r[3]) : "r"(addr));
}
__device__ __forceinline__ void mma16816(float* c, const uint32_t* a, const uint32_t* b) {
    asm volatile(
        "mma.sync.aligned.m16n8k16.row.col.f32.f16.f16.f32 "
        "{%0,%1,%2,%3}, {%4,%5,%6,%7}, {%8,%9}, {%0,%1,%2,%3};"
        : "+f"(c[0]), "+f"(c[1]), "+f"(c[2]), "+f"(c[3])
        : "r"(a[0]), "r"(a[1]), "r"(a[2]), "r"(a[3]), "r"(b[0]), "r"(b[1]));
}
__device__ __forceinline__ uint32_t packh2(float lo, float hi) {
    __half2 h = __floats2half2_rn(lo, hi);
    return *(uint32_t*)&h;
}
__device__ __forceinline__ void cp16(uint32_t saddr, const void* gaddr) {
    asm volatile("cp.async.cg.shared.global [%0], [%1], 16;" :: "r"(saddr), "l"(gaddr));
}
__device__ __forceinline__ void cp_commit() { asm volatile("cp.async.commit_group;"); }

// ---------------------------------------------------------------------------
// Raw-mma GEMM: C[M,Ncols] = A[M,768] @ Bm[768,Ncols] + bias
// CTA tile 128x128, 8 warps (2x4), warp tile 64x32, K-chunk 64,
// 2-stage cp.async double buffer, 256 threads, 2 CTAs/SM.
// MODE 0: A = g_x16, B = g_wq16 -> fp16 scatter into g_q/g_k/g_v
// MODE 1: A = g_ao,  B = g_wp16 -> fp32 row-major store to out
// ---------------------------------------------------------------------------
constexpr int TN = 128;
constexpr int KC = 64;
constexpr int NCH = Cc / KC;                 // 12
constexpr int ASTR = 72;
constexpr int BSTR = TN + 8;                 // 136
constexpr int A_ST_BYTES = 128 * ASTR * 2;   // 18432
constexpr int B_ST_BYTES = KC * BSTR * 2;    // 17408
constexpr int OFF_B0 = 2 * A_ST_BYTES;
constexpr int GEMM_SMEM = OFF_B0 + 2 * B_ST_BYTES;  // 71680 -> 2 CTAs/SM

template <int MODE>
__global__ void __launch_bounds__(256, 2) gemm_kernel(const float* __restrict__ bias,
                                                      float* __restrict__ out, int Ncols) {
    extern __shared__ __align__(16) char smc[];
    const uint32_t sbase = smem_u32(smc);

    const __half* A  = (MODE == 0) ? g_x16 : g_ao;
    const __half* Bm = (MODE == 0) ? g_wq16 : g_wp16;

    const int m0 = blockIdx.y * 128;
    const int n0 = blockIdx.x * TN;
    const int tid = threadIdx.x;
    const int warp = tid >> 5;
    const int lane = tid & 31;
    const int wm = warp >> 2;   // 0..1 -> 64-row band
    const int wn = warp & 3;    // 0..3 -> 32-col band

    auto load_chunk = [&](int ch, int buf) {
        const int k0 = ch * KC;
        const uint32_t abase = sbase + buf * A_ST_BYTES;
#pragma unroll
        for (int t = 0; t < 4; t++) {
            int idx = tid + t * 256;
            int r = idx >> 3, seg = idx & 7;
            cp16(abase + (uint32_t)(r * (ASTR * 2) + seg * 16),
                 A + (size_t)(m0 + r) * Cc + k0 + seg * 8);
        }
        const uint32_t bbase = sbase + OFF_B0 + buf * B_ST_BYTES;
#pragma unroll
        for (int t = 0; t < 4; t++) {
            int idx = tid + t * 256;
            int r = idx >> 4, seg = idx & 15;
            cp16(bbase + (uint32_t)(r * (BSTR * 2) + seg * 16),
                 Bm + (size_t)(k0 + r) * Ncols + n0 + seg * 8);
        }
        cp_commit();
    };

    float c[4][4][4];
#pragma unroll
    for (int mf = 0; mf < 4; mf++)
#pragma unroll
        for (int nt = 0; nt < 4; nt++)
#pragma unroll
            for (int e = 0; e < 4; e++) c[mf][nt][e] = 0.0f;

    load_chunk(0, 0);
    load_chunk(1, 1);

    const uint32_t a_row = (uint32_t)(wm * 64) + (lane & 15);
    const uint32_t a_coff = (uint32_t)(lane >> 4) * 8;
    const uint32_t b_krow = (uint32_t)(lane & 15);
    const uint32_t b_coff = (uint32_t)(wn * 32) + (uint32_t)(lane >> 4) * 8;

    for (int ch = 0; ch < NCH; ch++) {
        const int buf = ch & 1;
        if (ch + 1 < NCH) {
            asm volatile("cp.async.wait_group 1;" ::: "memory");
        } else {
            asm volatile("cp.async.wait_group 0;" ::: "memory");
        }
        __syncthreads();

        const uint32_t abase = sbase + buf * A_ST_BYTES;
        const uint32_t bbase = sbase + OFF_B0 + buf * B_ST_BYTES;
#pragma unroll
        for (int kk = 0; kk < 4; kk++) {
            uint32_t a[4][4];
#pragma unroll
            for (int mf = 0; mf < 4; mf++)
                ldsm4(a[mf], abase + ((a_row + mf * 16) * ASTR + kk * 16 + a_coff) * 2);
            uint32_t b[2][4];
#pragma unroll
            for (int np = 0; np < 2; np++)
                ldsm4t(b[np], bbase + ((kk * 16 + b_krow) * BSTR + b_coff + np * 16) * 2);
#pragma unroll
            for (int mf = 0; mf < 4; mf++)
#pragma unroll
                for (int nt = 0; nt < 4; nt++)
                    mma16816(c[mf][nt], a[mf], b[nt >> 1] + (nt & 1) * 2);
        }
        __syncthreads();
        if (ch + 2 < NCH) load_chunk(ch + 2, buf);
    }

    // ---- epilogue: bias + store ----
    const int ncol0 = n0 + wn * 32;
    float2 bias2[4];
#pragma unroll
    for (int nt = 0; nt < 4; nt++) {
        const int n = ncol0 + nt * 8 + (lane & 3) * 2;
        bias2[nt] = *(const float2*)(bias + n);
    }

    if (MODE == 1) {
#pragma unroll
        for (int mf = 0; mf < 4; mf++) {
            const int r0 = m0 + wm * 64 + mf * 16 + (lane >> 2);
#pragma unroll
            for (int nt = 0; nt < 4; nt++) {
                const int n = ncol0 + nt * 8 + (lane & 3) * 2;
                *(float2*)(out + (size_t)r0 * Ncols + n) =
                    make_float2(c[mf][nt][0] + bias2[nt].x, c[mf][nt][1] + bias2[nt].y);
                *(float2*)(out + (size_t)(r0 + 8) * Ncols + n) =
                    make_float2(c[mf][nt][2] + bias2[nt].x, c[mf][nt][3] + bias2[nt].y);
            }
        }
    } else {
        // 32-col warp band lies inside one 64-wide head chunk (ncol0 % 64 in {0,32})
        const int which = ncol0 / Cc;
        const int rem = ncol0 % Cc;
        const int h = rem >> 6;
        __half* arr = (which == 0) ? g_q : (which == 1) ? g_k : g_v;
#pragma unroll
        for (int mf = 0; mf < 4; mf++) {
            const int r0 = m0 + wm * 64 + mf * 16 + (lane >> 2);
            const int b0 = r0 >> 10, nr0 = r0 & 1023;
            const int r1 = r0 + 8;
            const int b1 = r1 >> 10, nr1 = r1 & 1023;
            __half* p0 = arr + (size_t)((b0 * Hh + h) * Nn + nr0) * HD;
            __half* p1 = arr + (size_t)((b1 * Hh + h) * Nn + nr1) * HD;
#pragma unroll
            for (int nt = 0; nt < 4; nt++) {
                const int d = (rem & 63) + nt * 8 + (lane & 3) * 2;
                *(__half2*)(p0 + d) =
                    __floats2half2_rn(c[mf][nt][0] + bias2[nt].x, c[mf][nt][1] + bias2[nt].y);
                *(__half2*)(p1 + d) =
                    __floats2half2_rn(c[mf][nt][2] + bias2[nt].x, c[mf][nt][3] + bias2[nt].y);
            }
        }
    }
}

// ---------------------------------------------------------------------------
// Flash attention, FA2-style register-resident, cp.async double-buffered K/V.
// (unchanged from R16)
// ---------------------------------------------------------------------------
constexpr int KT = 64;
constexpr int NIT = Nn / KT;              // 16
constexpr int Q_BYTES = 128 * 72 * 2;     // 18432
constexpr int KV_ST = KT * 72 * 2;        // 9216 per stage
constexpr int OFF_K = Q_BYTES;
constexpr int OFF_V = OFF_K + 2 * KV_ST;
constexpr int ATTN_SMEM = OFF_V + 2 * KV_ST;  // 55296

__global__ void __launch_bounds__(256, 2) attn_kernel() {
    extern __shared__ __align__(16) char smc[];
    const uint32_t sb = smem_u32(smc);
    __half* Qs = (__half*)smc;  // [128][72]

    const int tid = threadIdx.x;
    const int warp = tid >> 5;
    const int lane = tid & 31;
    const int n0 = blockIdx.x * 128;
    const int bh = blockIdx.y;
    const __half* Qg = g_q + (size_t)bh * Nn * HD;
    const __half* Kg = g_k + (size_t)bh * Nn * HD;
    const __half* Vg = g_v + (size_t)bh * Nn * HD;

    auto load_kv = [&](int kt, int buf) {
        const __half* Kp = Kg + (size_t)(kt * KT) * HD;
        const __half* Vp = Vg + (size_t)(kt * KT) * HD;
        const uint32_t kb = sb + OFF_K + buf * KV_ST;
        const uint32_t vb = sb + OFF_V + buf * KV_ST;
#pragma unroll
        for (int t = 0; t < 2; t++) {
            int idx = tid + t * 256;
            int r = idx >> 3, g = idx & 7;
            cp16(kb + (uint32_t)(r * 144 + g * 16), Kp + r * HD + g * 8);
            cp16(vb + (uint32_t)(r * 144 + g * 16), Vp + r * HD + g * 8);
        }
        cp_commit();
    };

    load_kv(0, 0);

    const __half2 sc = __floats2half2_rn(0.125f, 0.125f);
#pragma unroll
    for (int t = 0; t < 4; t++) {
        int idx = tid + t * 256;
        int r = idx >> 3, g = idx & 7;
        uint4 u = *(const uint4*)(Qg + (size_t)(n0 + r) * HD + g * 8);
        __half2* h = (__half2*)&u;
#pragma unroll
        for (int e = 0; e < 4; e++) h[e] = __hmul2(h[e], sc);
        *(uint4*)&Qs[r * 72 + g * 8] = u;
    }
    __syncthreads();

    uint32_t qa[4][4];
    {
        const uint32_t row = warp * 16 + (lane & 15);
        const uint32_t coff = (lane >> 4) * 8;
#pragma unroll
        for (int kk = 0; kk < 4; kk++)
            ldsm4(qa[kk], sb + (row * 72 + kk * 16 + coff) * 2);
    }

    float o[8][4];
#pragma unroll
    for (int h = 0; h < 8; h++)
#pragma unroll
        for (int e = 0; e < 4; e++) o[h][e] = 0.0f;
    float m0 = -1e30f, m1 = -1e30f, l0 = 0.0f, l1 = 0.0f;

    const uint32_t krow = (lane & 7);
    const uint32_t kcol = (lane >> 3) * 8;

    for (int kt = 0; kt < NIT; kt++) {
        const int buf = kt & 1;
        if (kt + 1 < NIT) {
            load_kv(kt + 1, buf ^ 1);
            asm volatile("cp.async.wait_group 1;" ::: "memory");
        } else {
            asm volatile("cp.async.wait_group 0;" ::: "memory");
        }
        __syncthreads();

        const uint32_t ks_u = sb + OFF_K + buf * KV_ST;
        const uint32_t vs_u = sb + OFF_V + buf * KV_ST;

        float s[8][4];
#pragma unroll
        for (int j = 0; j < 8; j++) {
            s[j][0] = s[j][1] = s[j][2] = s[j][3] = 0.0f;
            const uint32_t base = ks_u + (((j * 8 + krow) * 72) + kcol) * 2;
            uint32_t kr[4];
            ldsm4(kr, base);
            mma16816(s[j], qa[0], kr);
            mma16816(s[j], qa[1], kr + 2);
            ldsm4(kr, base + 64);
            mma16816(s[j], qa[2], kr);
            mma16816(s[j], qa[3], kr + 2);
        }

        float mx0 = -1e30f, mx1 = -1e30f;
#pragma unroll
        for (int j = 0; j < 8; j++) {
            mx0 = fmaxf(mx0, fmaxf(s[j][0], s[j][1]));
            mx1 = fmaxf(mx1, fmaxf(s[j][2], s[j][3]));
        }
        mx0 = fmaxf(mx0, __shfl_xor_sync(0xffffffffu, mx0, 1));
        mx0 = fmaxf(mx0, __shfl_xor_sync(0xffffffffu, mx0, 2));
        mx1 = fmaxf(mx1, __shfl_xor_sync(0xffffffffu, mx1, 1));
        mx1 = fmaxf(mx1, __shfl_xor_sync(0xffffffffu, mx1, 2));
        const float mn0 = fmaxf(m0, mx0), mn1 = fmaxf(m1, mx1);
        const float al0 = __expf(m0 - mn0), al1 = __expf(m1 - mn1);
        m0 = mn0; m1 = mn1;

        float sl0 = 0.0f, sl1 = 0.0f;
        uint32_t pa[4][4];
#pragma unroll
        for (int j = 0; j < 8; j++) {
            float p0 = __expf(s[j][0] - mn0);
            float p1 = __expf(s[j][1] - mn0);
            float p2 = __expf(s[j][2] - mn1);
            float p3 = __expf(s[j][3] - mn1);
            sl0 += p0 + p1;
            sl1 += p2 + p3;
            pa[j >> 1][(j & 1) * 2]     = packh2(p0, p1);
            pa[j >> 1][(j & 1) * 2 + 1] = packh2(p2, p3);
        }
        sl0 += __shfl_xor_sync(0xffffffffu, sl0, 1);
        sl0 += __shfl_xor_sync(0xffffffffu, sl0, 2);
        sl1 += __shfl_xor_sync(0xffffffffu, sl1, 1);
        sl1 += __shfl_xor_sync(0xffffffffu, sl1, 2);
        l0 = l0 * al0 + sl0;
        l1 = l1 * al1 + sl1;
#pragma unroll
        for (int h = 0; h < 8; h++) {
            o[h][0] *= al0; o[h][1] *= al0;
            o[h][2] *= al1; o[h][3] *= al1;
        }

#pragma unroll
        for (int kk = 0; kk < 4; kk++) {
            const uint32_t vbase = vs_u + (((kk * 16 + (lane & 15)) * 72) + (lane >> 4) * 8) * 2;
#pragma unroll
            for (int hp = 0; hp < 4; hp++) {
                uint32_t vr[4];
                ldsm4t(vr, vbase + hp * 32);
                mma16816(o[2 * hp],     pa[kk], vr);
                mma16816(o[2 * hp + 1], pa[kk], vr + 2);
            }
        }
        __syncthreads();
    }

    const int b = bh / Hh, head = bh % Hh;
    const float inv0 = 1.0f / l0, inv1 = 1.0f / l1;
    const int row0 = n0 + warp * 16 + (lane >> 2);
    __half* po0 = g_ao + (size_t)(b * Nn + row0) * Cc + head * HD;
    __half* po1 = po0 + (size_t)8 * Cc;
    const int cb = (lane & 3) * 2;
#pragma unroll
    for (int h = 0; h < 8; h++) {
        *(__half2*)(po0 + h * 8 + cb) = __floats2half2_rn(o[h][0] * inv0, o[h][1] * inv0);
        *(__half2*)(po1 + h * 8 + cb) = __floats2half2_rn(o[h][2] * inv1, o[h][3] * inv1);
    }
}

// ---------------------------------------------------------------------------
extern "C" void kernel_launch(void* const* d_in, const int* in_sizes, int n_in,
                              void* d_out, int out_size) {
    const float* x      = (const float*)d_in[0];
    const float* w_qkv  = (const float*)d_in[1];
    const float* b_qkv  = (const float*)d_in[2];
    const float* w_proj = (const float*)d_in[3];
    const float* b_proj = (const float*)d_in[4];
    float* out = (float*)d_out;

    static bool attr_set = false;
    if (!attr_set) {
        cudaFuncSetAttribute(gemm_kernel<0>, cudaFuncAttributeMaxDynamicSharedMemorySize,
                             GEMM_SMEM);
        cudaFuncSetAttribute(gemm_kernel<1>, cudaFuncAttributeMaxDynamicSharedMemorySize,
                             GEMM_SMEM);
        cudaFuncSetAttribute(attn_kernel, cudaFuncAttributeMaxDynamicSharedMemorySize,
                             ATTN_SMEM);
        attr_set = true;
    }

    // 0) fused fp32->fp16 converts
    cvt_all<<<(CVT_N2 / 4 + 255) / 256, 256>>>(x, w_qkv, w_proj);

    // 1) QKV GEMM: [8192,768] @ [768,2304] + bias -> fp16 scatter to Q/K/V
    gemm_kernel<0><<<dim3((3 * Cc) / TN, Mm / 128), 256, GEMM_SMEM>>>(b_qkv, nullptr, 3 * Cc);
    // 2) attention per (bh, 128-q-tile)
    attn_kernel<<<dim3(Nn / 128, Bb * Hh), 256, ATTN_SMEM>>>();
    // 3) output projection: [8192,768] @ [768,768] + bias -> d_out (fp32)
    gemm_kernel<1><<<dim3(Cc / TN, Mm / 128), 256, GEMM_SMEM>>>(b_proj, out, Cc);
}